// round 1
// baseline (speedup 1.0000x reference)
#include <cuda_runtime.h>
#include <stddef.h>

#define NROWS 16384
#define KN 32
#define DIN 256
#define DOUT 256
#define DCAT 512
#define BN_BLOCKS 128

// ---------------- scratch (static device memory; no allocation) ----------------
__device__ float g_A[DIN * DIN];      // Wk^T Wq
__device__ float g_B[DOUT * DIN];     // Wno Wv
__device__ float g_a0[DIN];           // Wk^T bq
__device__ float g_u[DIN];            // Wq^T bk
__device__ float g_b1[DOUT];          // Wno bv + bno
__device__ float g_c0[1];             // bk . bq
__device__ float g_C[NROWS];          // per-row energy constant
__device__ float g_QK[NROWS * DIN];   // A x_n + a0
__device__ float g_S[NROWS * DIN];    // attention-weighted neighbor sum
__device__ float g_O[NROWS * DCAT];   // concat(self_out, neigh_out)
__device__ float g_psum[BN_BLOCKS * DCAT];
__device__ float g_psum2[BN_BLOCKS * DCAT];
__device__ float g_scale[DCAT];
__device__ float g_shift[DCAT];

// ---------------- small precompute kernels ----------------
__global__ void precompute_vecs(const float* __restrict__ Wq, const float* __restrict__ bq,
                                const float* __restrict__ Wk, const float* __restrict__ bk,
                                const float* __restrict__ Wv, const float* __restrict__ bv,
                                const float* __restrict__ Wno, const float* __restrict__ bno) {
    int i = threadIdx.x;  // 256
    float a0 = 0.f, u = 0.f, b1 = 0.f;
    for (int o = 0; o < DOUT; o++) {
        a0 += Wk[o * DIN + i] * bq[o];
        u  += Wq[o * DIN + i] * bk[o];
        b1 += Wno[i * DOUT + o] * bv[o];
    }
    g_a0[i] = a0;
    g_u[i]  = u;
    g_b1[i] = b1 + bno[i];
    if (i == 0) {
        float c = 0.f;
        for (int o = 0; o < DOUT; o++) c += bk[o] * bq[o];
        g_c0[0] = c;
    }
}

__global__ void precompute_mats(const float* __restrict__ Wq, const float* __restrict__ Wk,
                                const float* __restrict__ Wv, const float* __restrict__ Wno) {
    __shared__ float colv[256];
    int r = blockIdx.x;
    int j = threadIdx.x;
    if (blockIdx.y == 0) {
        // g_A[r][j] = sum_o Wk[o][r] * Wq[o][j]
        colv[j] = Wk[j * DIN + r];
        __syncthreads();
        float s = 0.f;
        #pragma unroll 8
        for (int o = 0; o < DOUT; o++) s += colv[o] * Wq[o * DIN + j];
        g_A[r * DIN + j] = s;
    } else {
        // g_B[r][j] = sum_m Wno[r][m] * Wv[m][j]
        colv[j] = Wno[r * DOUT + j];
        __syncthreads();
        float s = 0.f;
        #pragma unroll 8
        for (int m = 0; m < DOUT; m++) s += colv[m] * Wv[m * DIN + j];
        g_B[r * DIN + j] = s;
    }
}

// C[n] = x_n . u + c0   (one warp per row)
__global__ void crow_kernel(const float* __restrict__ X) {
    int tid = threadIdx.x;
    int w = tid >> 5, lane = tid & 31;
    int row = blockIdx.x * 8 + w;
    const float* x = X + (size_t)row * DIN;
    float s = 0.f;
    #pragma unroll
    for (int j = 0; j < 8; j++) s += x[lane + 32 * j] * g_u[lane + 32 * j];
    #pragma unroll
    for (int off = 16; off; off >>= 1) s += __shfl_xor_sync(0xffffffffu, s, off);
    if (lane == 0) g_C[row] = s + g_c0[0];
}

// ---------------- generic fp32 SGEMM: C = A(MxK) * B(NxK)^T + bias ----------------
// MODE 0: plain store   MODE 1: gated-BN epilogue
template <int MODE>
__global__ __launch_bounds__(256, 2) void sgemm128(
    const float* __restrict__ Am, const float* __restrict__ Bm,
    const float* __restrict__ bias, float* __restrict__ Cm,
    int Kd, int ldc, int coloff,
    const float* __restrict__ Oin, const float* __restrict__ scale,
    const float* __restrict__ shift) {
    __shared__ float As[8][128];
    __shared__ float Bs[8][128];
    int tid = threadIdx.x;
    int tx = tid & 15, ty = tid >> 4;
    int bm = blockIdx.y * 128;
    int bn = blockIdx.x * 128;
    int lr = tid >> 1;
    int lk = (tid & 1) * 4;
    const float* Aptr = Am + (size_t)(bm + lr) * Kd + lk;
    const float* Bptr = Bm + (size_t)(bn + lr) * Kd + lk;

    float acc[8][8];
    #pragma unroll
    for (int i = 0; i < 8; i++)
        #pragma unroll
        for (int j = 0; j < 8; j++) acc[i][j] = 0.f;

    for (int k0 = 0; k0 < Kd; k0 += 8) {
        float4 av = *(const float4*)(Aptr + k0);
        float4 bv = *(const float4*)(Bptr + k0);
        As[lk + 0][lr] = av.x; As[lk + 1][lr] = av.y;
        As[lk + 2][lr] = av.z; As[lk + 3][lr] = av.w;
        Bs[lk + 0][lr] = bv.x; Bs[lk + 1][lr] = bv.y;
        Bs[lk + 2][lr] = bv.z; Bs[lk + 3][lr] = bv.w;
        __syncthreads();
        #pragma unroll
        for (int k = 0; k < 8; k++) {
            float a[8], b[8];
            #pragma unroll
            for (int c = 0; c < 8; c++) a[c] = As[k][ty * 8 + c];
            #pragma unroll
            for (int c = 0; c < 8; c++) b[c] = Bs[k][tx * 8 + c];
            #pragma unroll
            for (int i = 0; i < 8; i++)
                #pragma unroll
                for (int j = 0; j < 8; j++) acc[i][j] += a[i] * b[j];
        }
        __syncthreads();
    }

    #pragma unroll
    for (int ii = 0; ii < 8; ii++) {
        int row = bm + ty * 8 + ii;
        #pragma unroll
        for (int jj = 0; jj < 8; jj++) {
            int col = bn + tx * 8 + jj;
            float v = acc[ii][jj] + bias[col];
            if (MODE == 0) {
                Cm[(size_t)row * ldc + coloff + col] = v;
            } else {
                float o = Oin[(size_t)row * ldc + col];
                float bnv = o * scale[col] + shift[col];
                Cm[(size_t)row * ldc + col] = fmaxf(v, 0.f) * fmaxf(bnv, 0.f);
            }
        }
    }
}

// ---------------- attention: energies + softmax + weighted sum (one CTA/node) ----------------
#define XSTRIDE 264  // 256 + 8 pad -> conflict-free dual access pattern
__global__ __launch_bounds__(256) void attn_kernel(const float* __restrict__ nb) {
    __shared__ float xk[KN * XSTRIDE];
    __shared__ float qk[DIN];
    __shared__ float ek[KN];
    __shared__ float attw[KN];
    int n = blockIdx.x;
    int tid = threadIdx.x;

    const float4* src = (const float4*)(nb + (size_t)n * KN * DIN);
    #pragma unroll
    for (int j = 0; j < 8; j++) {
        int idx = tid + 256 * j;      // float4 index 0..2047
        int k = idx >> 6;
        int m = idx & 63;
        float4 v = src[idx];
        *(float4*)(&xk[k * XSTRIDE + m * 4]) = v;
    }
    qk[tid] = g_QK[(size_t)n * DIN + tid];
    __syncthreads();

    int w = tid >> 5, lane = tid & 31;
    int k = (w << 2) + (lane >> 3);     // 8 warps x 4 k each
    int cb = lane & 7;                  // 8 lanes per k
    const float* row = &xk[k * XSTRIDE];
    float s = 0.f, rs = 0.f;
    #pragma unroll
    for (int j = 0; j < 32; j++) {
        float v = row[cb + 8 * j];
        s += v * qk[cb + 8 * j];
        rs += v;
    }
    s  += __shfl_down_sync(0xffffffffu, s, 4);
    rs += __shfl_down_sync(0xffffffffu, rs, 4);
    s  += __shfl_down_sync(0xffffffffu, s, 2);
    rs += __shfl_down_sync(0xffffffffu, rs, 2);
    s  += __shfl_down_sync(0xffffffffu, s, 1);
    rs += __shfl_down_sync(0xffffffffu, rs, 1);
    if ((lane & 7) == 0) {
        float e = s + g_C[n];
        ek[k] = (rs == 0.f) ? 1e-12f : e;  // faithful: masked -> 1e-12, still in softmax
    }
    __syncthreads();

    if (w == 0) {
        float e = ek[lane];
        float m = e;
        #pragma unroll
        for (int off = 16; off; off >>= 1) m = fmaxf(m, __shfl_xor_sync(0xffffffffu, m, off));
        float ex = __expf(e - m);
        float sum = ex;
        #pragma unroll
        for (int off = 16; off; off >>= 1) sum += __shfl_xor_sync(0xffffffffu, sum, off);
        attw[lane] = ex / sum;
    }
    __syncthreads();

    float acc = 0.f;
    #pragma unroll
    for (int kk = 0; kk < KN; kk++) acc += attw[kk] * xk[kk * XSTRIDE + tid];
    g_S[(size_t)n * DIN + tid] = acc;
}

// ---------------- BatchNorm statistics (deterministic 2-stage) ----------------
__global__ void bn_stats() {
    int col = threadIdx.x;  // 512
    int blk = blockIdx.x;   // 128
    const float* p = g_O + (size_t)blk * 128 * DCAT + col;
    float s = 0.f, s2 = 0.f;
    #pragma unroll 4
    for (int r = 0; r < 128; r++) {
        float v = p[(size_t)r * DCAT];
        s += v; s2 += v * v;
    }
    g_psum[blk * DCAT + col] = s;
    g_psum2[blk * DCAT + col] = s2;
}

__global__ void bn_finalize(const float* __restrict__ gamma, const float* __restrict__ beta) {
    int col = threadIdx.x;  // 512
    float s = 0.f, s2 = 0.f;
    for (int b = 0; b < BN_BLOCKS; b++) {
        s += g_psum[b * DCAT + col];
        s2 += g_psum2[b * DCAT + col];
    }
    float mean = s * (1.f / NROWS);
    float var = s2 * (1.f / NROWS) - mean * mean;  // biased, matches jnp.var
    float sc = gamma[col] * rsqrtf(var + 1e-5f);
    g_scale[col] = sc;
    g_shift[col] = beta[col] - mean * sc;
}

// ---------------- launch ----------------
extern "C" void kernel_launch(void* const* d_in, const int* in_sizes, int n_in,
                              void* d_out, int out_size) {
    const float* X    = (const float*)d_in[0];
    const float* NB   = (const float*)d_in[1];
    const float* Wq   = (const float*)d_in[2];
    const float* bq   = (const float*)d_in[3];
    const float* Wk   = (const float*)d_in[4];
    const float* bk   = (const float*)d_in[5];
    const float* Wv   = (const float*)d_in[6];
    const float* bv   = (const float*)d_in[7];
    const float* Wno  = (const float*)d_in[8];
    const float* bno  = (const float*)d_in[9];
    const float* Wio  = (const float*)d_in[10];
    const float* bio  = (const float*)d_in[11];
    const float* Wg   = (const float*)d_in[12];
    const float* bg   = (const float*)d_in[13];
    const float* gam  = (const float*)d_in[14];
    const float* bet  = (const float*)d_in[15];
    float* out = (float*)d_out;

    float *pA, *pB, *pa0, *pb1, *pQK, *pS, *pO, *pscale, *pshift;
    cudaGetSymbolAddress((void**)&pA, g_A);
    cudaGetSymbolAddress((void**)&pB, g_B);
    cudaGetSymbolAddress((void**)&pa0, g_a0);
    cudaGetSymbolAddress((void**)&pb1, g_b1);
    cudaGetSymbolAddress((void**)&pQK, g_QK);
    cudaGetSymbolAddress((void**)&pS, g_S);
    cudaGetSymbolAddress((void**)&pO, g_O);
    cudaGetSymbolAddress((void**)&pscale, g_scale);
    cudaGetSymbolAddress((void**)&pshift, g_shift);

    // 1. tiny precomputes: A = Wk^T Wq, B = Wno Wv, bias folds
    precompute_vecs<<<1, 256>>>(Wq, bq, Wk, bk, Wv, bv, Wno, bno);
    precompute_mats<<<dim3(256, 2), 256>>>(Wq, Wk, Wv, Wno);
    // 2. per-row energy constant C[n] = x_n . u + c0
    crow_kernel<<<NROWS / 8, 256>>>(X);
    // 3. QK = X A^T + a0
    sgemm128<0><<<dim3(DIN / 128, NROWS / 128), 256>>>(X, pA, pa0, pQK, DIN, DIN, 0,
                                                       nullptr, nullptr, nullptr);
    // 4. attention: energies/softmax/weighted-sum (single pass over 512MB)
    attn_kernel<<<NROWS, 256>>>(NB);
    // 5. O[:, :256] = X Wio^T + bio
    sgemm128<0><<<dim3(DOUT / 128, NROWS / 128), 256>>>(X, Wio, bio, pO, DIN, DCAT, 0,
                                                        nullptr, nullptr, nullptr);
    // 6. O[:, 256:] = S B^T + b1
    sgemm128<0><<<dim3(DOUT / 128, NROWS / 128), 256>>>(pS, pB, pb1, pO, DIN, DCAT, DOUT,
                                                        nullptr, nullptr, nullptr);
    // 7. BN statistics (deterministic)
    bn_stats<<<BN_BLOCKS, DCAT>>>();
    bn_finalize<<<1, DCAT>>>(gam, bet);
    // 8. out = relu(O Wg^T + bg) * relu(BN(O))
    sgemm128<1><<<dim3(DCAT / 128, NROWS / 128), 256>>>(pO, Wg, bg, out, DCAT, DCAT, 0,
                                                        pO, pscale, pshift);
}

// round 10
// speedup vs baseline: 1.5846x; 1.5846x over previous
#include <cuda_runtime.h>
#include <cuda_bf16.h>
#include <cstdint>
#include <stddef.h>

#define NROWS 16384
#define KN 32
#define DIN 256
#define DOUT 256
#define DCAT 512
#define BN_BLOCKS 128

// ---------------- scratch (static device memory; no allocation) ----------------
__device__ float g_A[DIN * DIN];      // Wk^T Wq
__device__ float g_B[DOUT * DIN];     // Wno Wv
__device__ float g_a0[DIN];           // Wk^T bq
__device__ float g_u[DIN];            // Wq^T bk
__device__ float g_b1[DOUT];          // Wno bv + bno
__device__ float g_c0[1];             // bk . bq
__device__ float g_C[NROWS];          // per-row energy constant
__device__ float g_QK[NROWS * DIN];   // A x_n + a0
__device__ float g_S[NROWS * DIN];    // attention-weighted neighbor sum
__device__ float g_O[NROWS * DCAT];   // concat(self_out, neigh_out)
__device__ float g_psum[BN_BLOCKS * DCAT];
__device__ float g_psum2[BN_BLOCKS * DCAT];
__device__ float g_scale[DCAT];
__device__ float g_shift[DCAT];

// ---------------- mma.sync bf16 helpers (baseline PTX, works on plain sm_103) ----------------
__device__ __forceinline__ void mma16816(float* c, const uint32_t* a, uint32_t b0, uint32_t b1) {
    asm volatile(
        "mma.sync.aligned.m16n8k16.row.col.f32.bf16.bf16.f32 "
        "{%0,%1,%2,%3}, {%4,%5,%6,%7}, {%8,%9}, {%0,%1,%2,%3};"
        : "+f"(c[0]), "+f"(c[1]), "+f"(c[2]), "+f"(c[3])
        : "r"(a[0]), "r"(a[1]), "r"(a[2]), "r"(a[3]), "r"(b0), "r"(b1));
}

// fp32 -> bf16 hi/lo split, packed pairs (lower k in low 16 bits)
__device__ __forceinline__ void cvt_hilo(float4 v, uint2& hi, uint2& lo) {
    __nv_bfloat16 hx = __float2bfloat16(v.x), hy = __float2bfloat16(v.y);
    __nv_bfloat16 hz = __float2bfloat16(v.z), hw = __float2bfloat16(v.w);
    __nv_bfloat16 lx = __float2bfloat16(v.x - __bfloat162float(hx));
    __nv_bfloat16 ly = __float2bfloat16(v.y - __bfloat162float(hy));
    __nv_bfloat16 lz = __float2bfloat16(v.z - __bfloat162float(hz));
    __nv_bfloat16 lw = __float2bfloat16(v.w - __bfloat162float(hw));
    hi.x = ((uint32_t)__bfloat16_as_ushort(hy) << 16) | __bfloat16_as_ushort(hx);
    hi.y = ((uint32_t)__bfloat16_as_ushort(hw) << 16) | __bfloat16_as_ushort(hz);
    lo.x = ((uint32_t)__bfloat16_as_ushort(ly) << 16) | __bfloat16_as_ushort(lx);
    lo.y = ((uint32_t)__bfloat16_as_ushort(lw) << 16) | __bfloat16_as_ushort(lz);
}

// ---------------- tensor-core bf16x3 GEMM: C = A(MxK) * B(NxK)^T + bias ----------------
// MODE 0: plain store   MODE 1: gated-BN epilogue
// 128x128 CTA tile, 8 warps (2x4), warp tile m64n32; K chunked by 32; double-buffered SMEM.
// SMEM plane layout [128 rows][20 words] (pitch 40 bf16): fragment loads are bank-conflict-free.
#define PLANE_W 2560                   // words per plane (128*20)
#define BUF_W (4 * PLANE_W)            // A_hi, A_lo, B_hi, B_lo
#define SMEM_WORDS (2 * BUF_W)         // double buffer: 20480 words = 80KB

__device__ __forceinline__ void gemm_fetch(const float* __restrict__ Afp,
                                           const float* __restrict__ Bfp,
                                           int bm, int bn, int kf4, int c, int tid,
                                           float4* pa, float4* pb) {
    #pragma unroll
    for (int j = 0; j < 4; j++) {
        int fidx = tid + 256 * j;           // 0..1023
        int row = fidx >> 3, m = fidx & 7;  // 128 rows x 8 float4
        pa[j] = ((const float4*)Afp)[(size_t)(bm + row) * kf4 + c * 8 + m];
        pb[j] = ((const float4*)Bfp)[(size_t)(bn + row) * kf4 + c * 8 + m];
    }
}

__device__ __forceinline__ void gemm_store(uint32_t* base, int tid,
                                           const float4* pa, const float4* pb) {
    uint32_t* Ah = base;
    uint32_t* Al = base + PLANE_W;
    uint32_t* Bh = base + 2 * PLANE_W;
    uint32_t* Bl = base + 3 * PLANE_W;
    #pragma unroll
    for (int j = 0; j < 4; j++) {
        int fidx = tid + 256 * j;
        int row = fidx >> 3, m = fidx & 7;
        int w = row * 20 + 2 * m;
        uint2 hi, lo;
        cvt_hilo(pa[j], hi, lo);
        *(uint2*)&Ah[w] = hi;
        *(uint2*)&Al[w] = lo;
        cvt_hilo(pb[j], hi, lo);
        *(uint2*)&Bh[w] = hi;
        *(uint2*)&Bl[w] = lo;
    }
}

__device__ __forceinline__ void gemm_compute(const uint32_t* base, int wrow, int wcol,
                                             int g, int tig, float acc[4][4][4]) {
    const uint32_t* Ah = base;
    const uint32_t* Al = base + PLANE_W;
    const uint32_t* Bh = base + 2 * PLANE_W;
    const uint32_t* Bl = base + 3 * PLANE_W;
    #pragma unroll
    for (int s = 0; s < 2; s++) {          // two k16 steps per 32-chunk
        int ko = s * 8 + tig;
        uint32_t ah[4][4], al[4][4];
        #pragma unroll
        for (int mt = 0; mt < 4; mt++) {
            int r0 = (wrow + mt * 16 + g) * 20;
            int r1 = r0 + 160;             // +8 rows
            ah[mt][0] = Ah[r0 + ko]; ah[mt][1] = Ah[r1 + ko];
            ah[mt][2] = Ah[r0 + ko + 4]; ah[mt][3] = Ah[r1 + ko + 4];
            al[mt][0] = Al[r0 + ko]; al[mt][1] = Al[r1 + ko];
            al[mt][2] = Al[r0 + ko + 4]; al[mt][3] = Al[r1 + ko + 4];
        }
        #pragma unroll
        for (int nt = 0; nt < 4; nt++) {
            int rb = (wcol + nt * 8 + g) * 20;
            uint32_t bh0 = Bh[rb + ko], bh1 = Bh[rb + ko + 4];
            uint32_t bl0 = Bl[rb + ko], bl1 = Bl[rb + ko + 4];
            #pragma unroll
            for (int mt = 0; mt < 4; mt++) {
                mma16816(acc[mt][nt], ah[mt], bh0, bh1);   // hi*hi
                mma16816(acc[mt][nt], al[mt], bh0, bh1);   // lo*hi
                mma16816(acc[mt][nt], ah[mt], bl0, bl1);   // hi*lo
            }
        }
    }
}

template <int MODE>
__global__ void __launch_bounds__(256, 1) gemm_mma(
    const float* __restrict__ Afp, const float* __restrict__ Bfp,
    const float* __restrict__ bias, float* __restrict__ Cm,
    int Kd, int ldc, int coloff,
    const float* __restrict__ Oin, const float* __restrict__ scale,
    const float* __restrict__ shift) {
    extern __shared__ uint32_t smw[];
    int tid = threadIdx.x;
    int lane = tid & 31, wid = tid >> 5;
    int bm = blockIdx.y * 128, bn = blockIdx.x * 128;
    int g = lane >> 2, tig = lane & 3;
    int wrow = (wid >> 2) * 64, wcol = (wid & 3) * 32;

    float acc[4][4][4];
    #pragma unroll
    for (int a = 0; a < 4; a++)
        #pragma unroll
        for (int b = 0; b < 4; b++)
            #pragma unroll
            for (int d = 0; d < 4; d++) acc[a][b][d] = 0.f;

    const int kf4 = Kd >> 2;
    const int nch = Kd >> 5;

    {   // prologue
        float4 pa[4], pb[4];
        gemm_fetch(Afp, Bfp, bm, bn, kf4, 0, tid, pa, pb);
        gemm_store(smw, tid, pa, pb);
    }
    __syncthreads();

    for (int c = 0; c < nch; c++) {
        float4 pa[4], pb[4];
        if (c + 1 < nch) gemm_fetch(Afp, Bfp, bm, bn, kf4, c + 1, tid, pa, pb);
        gemm_compute(smw + (c & 1) * BUF_W, wrow, wcol, g, tig, acc);
        if (c + 1 < nch) {
            gemm_store(smw + ((c + 1) & 1) * BUF_W, tid, pa, pb);
            __syncthreads();
        }
    }

    // epilogue: c0,c1 -> (row, col..col+1); c2,c3 -> (row+8, col..col+1)
    #pragma unroll
    for (int mt = 0; mt < 4; mt++) {
        int row0 = bm + wrow + mt * 16 + g;
        #pragma unroll
        for (int nt = 0; nt < 4; nt++) {
            int col = bn + wcol + nt * 8 + 2 * tig;
            float* a4 = acc[mt][nt];
            float2 v0 = {a4[0] + bias[col], a4[1] + bias[col + 1]};
            float2 v1 = {a4[2] + bias[col], a4[3] + bias[col + 1]};
            if (MODE == 1) {
                float sc0 = scale[col], sc1 = scale[col + 1];
                float sh0 = shift[col], sh1 = shift[col + 1];
                float2 o0 = *(const float2*)(Oin + (size_t)row0 * ldc + col);
                float2 o1 = *(const float2*)(Oin + (size_t)(row0 + 8) * ldc + col);
                v0.x = fmaxf(v0.x, 0.f) * fmaxf(o0.x * sc0 + sh0, 0.f);
                v0.y = fmaxf(v0.y, 0.f) * fmaxf(o0.y * sc1 + sh1, 0.f);
                v1.x = fmaxf(v1.x, 0.f) * fmaxf(o1.x * sc0 + sh0, 0.f);
                v1.y = fmaxf(v1.y, 0.f) * fmaxf(o1.y * sc1 + sh1, 0.f);
            }
            *(float2*)(Cm + (size_t)row0 * ldc + coloff + col) = v0;
            *(float2*)(Cm + (size_t)(row0 + 8) * ldc + coloff + col) = v1;
        }
    }
}

// ---------------- small precompute kernels (fp32) ----------------
__global__ void precompute_vecs(const float* __restrict__ Wq, const float* __restrict__ bq,
                                const float* __restrict__ Wk, const float* __restrict__ bk,
                                const float* __restrict__ Wv, const float* __restrict__ bv,
                                const float* __restrict__ Wno, const float* __restrict__ bno) {
    int i = threadIdx.x;  // 256
    float a0 = 0.f, u = 0.f, b1 = 0.f;
    for (int o = 0; o < DOUT; o++) {
        a0 += Wk[o * DIN + i] * bq[o];
        u  += Wq[o * DIN + i] * bk[o];
        b1 += Wno[i * DOUT + o] * bv[o];
    }
    g_a0[i] = a0;
    g_u[i]  = u;
    g_b1[i] = b1 + bno[i];
    if (i == 0) {
        float c = 0.f;
        for (int o = 0; o < DOUT; o++) c += bk[o] * bq[o];
        g_c0[0] = c;
    }
}

__global__ void precompute_mats(const float* __restrict__ Wq, const float* __restrict__ Wk,
                                const float* __restrict__ Wv, const float* __restrict__ Wno) {
    __shared__ float colv[256];
    int r = blockIdx.x;
    int j = threadIdx.x;
    if (blockIdx.y == 0) {
        colv[j] = Wk[j * DIN + r];
        __syncthreads();
        float s = 0.f;
        #pragma unroll 8
        for (int o = 0; o < DOUT; o++) s += colv[o] * Wq[o * DIN + j];
        g_A[r * DIN + j] = s;
    } else {
        colv[j] = Wno[r * DOUT + j];
        __syncthreads();
        float s = 0.f;
        #pragma unroll 8
        for (int m = 0; m < DOUT; m++) s += colv[m] * Wv[m * DIN + j];
        g_B[r * DIN + j] = s;
    }
}

// C[n] = x_n . u + c0   (one warp per row)
__global__ void crow_kernel(const float* __restrict__ X) {
    int tid = threadIdx.x;
    int w = tid >> 5, lane = tid & 31;
    int row = blockIdx.x * 8 + w;
    const float* x = X + (size_t)row * DIN;
    float s = 0.f;
    #pragma unroll
    for (int j = 0; j < 8; j++) s += x[lane + 32 * j] * g_u[lane + 32 * j];
    #pragma unroll
    for (int off = 16; off; off >>= 1) s += __shfl_xor_sync(0xffffffffu, s, off);
    if (lane == 0) g_C[row] = s + g_c0[0];
}

// ---------------- attention: energies + softmax + weighted sum (one CTA/node) ----------------
#define XSTRIDE 264
__global__ void __launch_bounds__(256) attn_kernel(const float* __restrict__ nb) {
    __shared__ float xk[KN * XSTRIDE];
    __shared__ float qk[DIN];
    __shared__ float ek[KN];
    __shared__ float attw[KN];
    int n = blockIdx.x;
    int tid = threadIdx.x;

    const float4* src = (const float4*)(nb + (size_t)n * KN * DIN);
    #pragma unroll
    for (int j = 0; j < 8; j++) {
        int idx = tid + 256 * j;
        int k = idx >> 6;
        int m = idx & 63;
        float4 v = src[idx];
        *(float4*)(&xk[k * XSTRIDE + m * 4]) = v;
    }
    qk[tid] = g_QK[(size_t)n * DIN + tid];
    __syncthreads();

    int w = tid >> 5, lane = tid & 31;
    int k = (w << 2) + (lane >> 3);
    int cb = lane & 7;
    const float* row = &xk[k * XSTRIDE];
    float s = 0.f, rs = 0.f;
    #pragma unroll
    for (int j = 0; j < 32; j++) {
        float v = row[cb + 8 * j];
        s += v * qk[cb + 8 * j];
        rs += v;
    }
    s  += __shfl_down_sync(0xffffffffu, s, 4);
    rs += __shfl_down_sync(0xffffffffu, rs, 4);
    s  += __shfl_down_sync(0xffffffffu, s, 2);
    rs += __shfl_down_sync(0xffffffffu, rs, 2);
    s  += __shfl_down_sync(0xffffffffu, s, 1);
    rs += __shfl_down_sync(0xffffffffu, rs, 1);
    if ((lane & 7) == 0) {
        float e = s + g_C[n];
        ek[k] = (rs == 0.f) ? 1e-12f : e;
    }
    __syncthreads();

    if (w == 0) {
        float e = ek[lane];
        float m = e;
        #pragma unroll
        for (int off = 16; off; off >>= 1) m = fmaxf(m, __shfl_xor_sync(0xffffffffu, m, off));
        float ex = __expf(e - m);
        float sum = ex;
        #pragma unroll
        for (int off = 16; off; off >>= 1) sum += __shfl_xor_sync(0xffffffffu, sum, off);
        attw[lane] = ex / sum;
    }
    __syncthreads();

    float acc = 0.f;
    #pragma unroll
    for (int kk = 0; kk < KN; kk++) acc += attw[kk] * xk[kk * XSTRIDE + tid];
    g_S[(size_t)n * DIN + tid] = acc;
}

// ---------------- BatchNorm statistics (deterministic 2-stage) ----------------
__global__ void bn_stats() {
    int col = threadIdx.x;  // 512
    int blk = blockIdx.x;   // 128
    const float* p = g_O + (size_t)blk * 128 * DCAT + col;
    float s = 0.f, s2 = 0.f;
    #pragma unroll 4
    for (int r = 0; r < 128; r++) {
        float v = p[(size_t)r * DCAT];
        s += v; s2 += v * v;
    }
    g_psum[blk * DCAT + col] = s;
    g_psum2[blk * DCAT + col] = s2;
}

__global__ void bn_finalize(const float* __restrict__ gamma, const float* __restrict__ beta) {
    int col = threadIdx.x;  // 512
    float s = 0.f, s2 = 0.f;
    for (int b = 0; b < BN_BLOCKS; b++) {
        s += g_psum[b * DCAT + col];
        s2 += g_psum2[b * DCAT + col];
    }
    float mean = s * (1.f / NROWS);
    float var = s2 * (1.f / NROWS) - mean * mean;
    float sc = gamma[col] * rsqrtf(var + 1e-5f);
    g_scale[col] = sc;
    g_shift[col] = beta[col] - mean * sc;
}

// ---------------- launch ----------------
extern "C" void kernel_launch(void* const* d_in, const int* in_sizes, int n_in,
                              void* d_out, int out_size) {
    const float* X    = (const float*)d_in[0];
    const float* NB   = (const float*)d_in[1];
    const float* Wq   = (const float*)d_in[2];
    const float* bq   = (const float*)d_in[3];
    const float* Wk   = (const float*)d_in[4];
    const float* bk   = (const float*)d_in[5];
    const float* Wv   = (const float*)d_in[6];
    const float* bv   = (const float*)d_in[7];
    const float* Wno  = (const float*)d_in[8];
    const float* bno  = (const float*)d_in[9];
    const float* Wio  = (const float*)d_in[10];
    const float* bio  = (const float*)d_in[11];
    const float* Wg   = (const float*)d_in[12];
    const float* bg   = (const float*)d_in[13];
    const float* gam  = (const float*)d_in[14];
    const float* bet  = (const float*)d_in[15];
    float* out = (float*)d_out;

    float *pA, *pB, *pa0, *pb1, *pQK, *pS, *pO, *pscale, *pshift;
    cudaGetSymbolAddress((void**)&pA, g_A);
    cudaGetSymbolAddress((void**)&pB, g_B);
    cudaGetSymbolAddress((void**)&pa0, g_a0);
    cudaGetSymbolAddress((void**)&pb1, g_b1);
    cudaGetSymbolAddress((void**)&pQK, g_QK);
    cudaGetSymbolAddress((void**)&pS, g_S);
    cudaGetSymbolAddress((void**)&pO, g_O);
    cudaGetSymbolAddress((void**)&pscale, g_scale);
    cudaGetSymbolAddress((void**)&pshift, g_shift);

    const int smem_bytes = SMEM_WORDS * 4;  // 80KB
    cudaFuncSetAttribute(gemm_mma<0>, cudaFuncAttributeMaxDynamicSharedMemorySize, smem_bytes);
    cudaFuncSetAttribute(gemm_mma<1>, cudaFuncAttributeMaxDynamicSharedMemorySize, smem_bytes);

    // 1. tiny precomputes
    precompute_vecs<<<1, 256>>>(Wq, bq, Wk, bk, Wv, bv, Wno, bno);
    precompute_mats<<<dim3(256, 2), 256>>>(Wq, Wk, Wv, Wno);
    // 2. per-row energy constant
    crow_kernel<<<NROWS / 8, 256>>>(X);
    // 3. QK = X A^T + a0   (tensor cores via mma.sync)
    gemm_mma<0><<<dim3(2, 128), 256, smem_bytes>>>(X, pA, pa0, pQK, DIN, DIN, 0,
                                                   nullptr, nullptr, nullptr);
    // 4. attention
    attn_kernel<<<NROWS, 256>>>(NB);
    // 5. O[:, :256] = X Wio^T + bio
    gemm_mma<0><<<dim3(2, 128), 256, smem_bytes>>>(X, Wio, bio, pO, DIN, DCAT, 0,
                                                   nullptr, nullptr, nullptr);
    // 6. O[:, 256:] = S B^T + b1
    gemm_mma<0><<<dim3(2, 128), 256, smem_bytes>>>(pS, pB, pb1, pO, DIN, DCAT, DOUT,
                                                   nullptr, nullptr, nullptr);
    // 7. BN statistics
    bn_stats<<<BN_BLOCKS, DCAT>>>();
    bn_finalize<<<1, DCAT>>>(gam, bet);
    // 8. out = relu(O Wg^T + bg) * relu(BN(O))
    gemm_mma<1><<<dim3(4, 128), 256, smem_bytes>>>(pO, Wg, bg, out, DCAT, DCAT, 0,
                                                   pO, pscale, pshift);
}

// round 15
// speedup vs baseline: 1.6126x; 1.0177x over previous
#include <cuda_runtime.h>
#include <cuda_bf16.h>
#include <cstdint>
#include <stddef.h>

#define NROWS 16384
#define KN 32
#define DIN 256
#define DOUT 256
#define DCAT 512
#define BN_BLOCKS 128

// ---------------- scratch (static device memory; no allocation) ----------------
__device__ float g_A[DIN * DIN];      // Wk^T Wq
__device__ float g_B[DOUT * DIN];     // Wno Wv
__device__ float g_a0[DIN];           // Wk^T bq
__device__ float g_u[DIN];            // Wq^T bk
__device__ float g_b1[DOUT];          // Wno bv + bno
__device__ float g_c0[1];             // bk . bq
__device__ float g_C[NROWS];          // per-row energy constant
__device__ float g_QK[NROWS * DIN];   // A x_n + a0
__device__ float g_S[NROWS * DIN];    // attention-weighted neighbor sum
__device__ float g_O[NROWS * DCAT];   // concat(self_out, neigh_out)
__device__ float g_psum[BN_BLOCKS * DCAT];
__device__ float g_psum2[BN_BLOCKS * DCAT];
__device__ float g_scale[DCAT];
__device__ float g_shift[DCAT];

// ---------------- mma.sync bf16 helpers (baseline PTX, works on plain sm_103) ----------------
__device__ __forceinline__ void mma16816(float* c, const uint32_t* a, uint32_t b0, uint32_t b1) {
    asm volatile(
        "mma.sync.aligned.m16n8k16.row.col.f32.bf16.bf16.f32 "
        "{%0,%1,%2,%3}, {%4,%5,%6,%7}, {%8,%9}, {%0,%1,%2,%3};"
        : "+f"(c[0]), "+f"(c[1]), "+f"(c[2]), "+f"(c[3])
        : "r"(a[0]), "r"(a[1]), "r"(a[2]), "r"(a[3]), "r"(b0), "r"(b1));
}

// fp32 -> bf16 hi/lo split, packed pairs (lower k in low 16 bits)
__device__ __forceinline__ void cvt_hilo(float4 v, uint2& hi, uint2& lo) {
    __nv_bfloat16 hx = __float2bfloat16(v.x), hy = __float2bfloat16(v.y);
    __nv_bfloat16 hz = __float2bfloat16(v.z), hw = __float2bfloat16(v.w);
    __nv_bfloat16 lx = __float2bfloat16(v.x - __bfloat162float(hx));
    __nv_bfloat16 ly = __float2bfloat16(v.y - __bfloat162float(hy));
    __nv_bfloat16 lz = __float2bfloat16(v.z - __bfloat162float(hz));
    __nv_bfloat16 lw = __float2bfloat16(v.w - __bfloat162float(hw));
    hi.x = ((uint32_t)__bfloat16_as_ushort(hy) << 16) | __bfloat16_as_ushort(hx);
    hi.y = ((uint32_t)__bfloat16_as_ushort(hw) << 16) | __bfloat16_as_ushort(hz);
    lo.x = ((uint32_t)__bfloat16_as_ushort(ly) << 16) | __bfloat16_as_ushort(lx);
    lo.y = ((uint32_t)__bfloat16_as_ushort(lw) << 16) | __bfloat16_as_ushort(lz);
}

// ---------------- tensor-core bf16x3 GEMM: C = A(MxK) * B(NxK)^T + bias ----------------
// MODE 0: plain store   MODE 1: gated-BN epilogue
// CTA tile 128(M)x64(N), 8 warps (4x2), warp tile m32n32; K chunked by 32; double-buffered.
// Low regs (~110) + 60KB SMEM -> 2 CTAs/SM so tensor pipe stays fed during store/sync.
// SMEM plane pitch 20 words: fragment word-index mod 32 = 20g+tig covers all 32 banks.
#define A_PLANE_W 2560                 // 128 rows * 20 words
#define B_PLANE_W 1280                 // 64 rows * 20 words
#define BUF_W (2 * A_PLANE_W + 2 * B_PLANE_W)   // Ah, Al, Bh, Bl = 7680 words
#define SMEM_WORDS (2 * BUF_W)                  // double buffer: 15360 words = 60KB

__device__ __forceinline__ void gemm_fetch(const float* __restrict__ Afp,
                                           const float* __restrict__ Bfp,
                                           int bm, int bn, int kf4, int c, int tid,
                                           float4* pa, float4* pb) {
    #pragma unroll
    for (int j = 0; j < 4; j++) {
        int fidx = tid + 256 * j;           // 0..1023 : 128 rows x 8 float4
        int row = fidx >> 3, m = fidx & 7;
        pa[j] = ((const float4*)Afp)[(size_t)(bm + row) * kf4 + c * 8 + m];
    }
    #pragma unroll
    for (int j = 0; j < 2; j++) {
        int fidx = tid + 256 * j;           // 0..511 : 64 rows x 8 float4
        int row = fidx >> 3, m = fidx & 7;
        pb[j] = ((const float4*)Bfp)[(size_t)(bn + row) * kf4 + c * 8 + m];
    }
}

__device__ __forceinline__ void gemm_store(uint32_t* base, int tid,
                                           const float4* pa, const float4* pb) {
    uint32_t* Ah = base;
    uint32_t* Al = base + A_PLANE_W;
    uint32_t* Bh = base + 2 * A_PLANE_W;
    uint32_t* Bl = base + 2 * A_PLANE_W + B_PLANE_W;
    #pragma unroll
    for (int j = 0; j < 4; j++) {
        int fidx = tid + 256 * j;
        int row = fidx >> 3, m = fidx & 7;
        int w = row * 20 + 2 * m;
        uint2 hi, lo;
        cvt_hilo(pa[j], hi, lo);
        *(uint2*)&Ah[w] = hi;
        *(uint2*)&Al[w] = lo;
    }
    #pragma unroll
    for (int j = 0; j < 2; j++) {
        int fidx = tid + 256 * j;
        int row = fidx >> 3, m = fidx & 7;
        int w = row * 20 + 2 * m;
        uint2 hi, lo;
        cvt_hilo(pb[j], hi, lo);
        *(uint2*)&Bh[w] = hi;
        *(uint2*)&Bl[w] = lo;
    }
}

__device__ __forceinline__ void gemm_compute(const uint32_t* base, int wrow, int wcol,
                                             int g, int tig, float acc[2][4][4]) {
    const uint32_t* Ah = base;
    const uint32_t* Al = base + A_PLANE_W;
    const uint32_t* Bh = base + 2 * A_PLANE_W;
    const uint32_t* Bl = base + 2 * A_PLANE_W + B_PLANE_W;
    #pragma unroll
    for (int s = 0; s < 2; s++) {          // two k16 steps per 32-chunk
        int ko = s * 8 + tig;
        uint32_t ah[2][4], al[2][4];
        #pragma unroll
        for (int mt = 0; mt < 2; mt++) {
            int r0 = (wrow + mt * 16 + g) * 20;
            int r1 = r0 + 160;             // +8 rows
            ah[mt][0] = Ah[r0 + ko]; ah[mt][1] = Ah[r1 + ko];
            ah[mt][2] = Ah[r0 + ko + 4]; ah[mt][3] = Ah[r1 + ko + 4];
            al[mt][0] = Al[r0 + ko]; al[mt][1] = Al[r1 + ko];
            al[mt][2] = Al[r0 + ko + 4]; al[mt][3] = Al[r1 + ko + 4];
        }
        #pragma unroll
        for (int nt = 0; nt < 4; nt++) {
            int rb = (wcol + nt * 8 + g) * 20;
            uint32_t bh0 = Bh[rb + ko], bh1 = Bh[rb + ko + 4];
            uint32_t bl0 = Bl[rb + ko], bl1 = Bl[rb + ko + 4];
            #pragma unroll
            for (int mt = 0; mt < 2; mt++) {
                mma16816(acc[mt][nt], ah[mt], bh0, bh1);   // hi*hi
                mma16816(acc[mt][nt], al[mt], bh0, bh1);   // lo*hi
                mma16816(acc[mt][nt], ah[mt], bl0, bl1);   // hi*lo
            }
        }
    }
}

template <int MODE>
__global__ void __launch_bounds__(256, 2) gemm_mma(
    const float* __restrict__ Afp, const float* __restrict__ Bfp,
    const float* __restrict__ bias, float* __restrict__ Cm,
    int Kd, int ldc, int coloff,
    const float* __restrict__ Oin, const float* __restrict__ scale,
    const float* __restrict__ shift) {
    extern __shared__ uint32_t smw[];
    int tid = threadIdx.x;
    int lane = tid & 31, wid = tid >> 5;
    int bm = blockIdx.y * 128, bn = blockIdx.x * 64;
    int g = lane >> 2, tig = lane & 3;
    int wrow = (wid >> 1) * 32, wcol = (wid & 1) * 32;

    float acc[2][4][4];
    #pragma unroll
    for (int a = 0; a < 2; a++)
        #pragma unroll
        for (int b = 0; b < 4; b++)
            #pragma unroll
            for (int d = 0; d < 4; d++) acc[a][b][d] = 0.f;

    const int kf4 = Kd >> 2;
    const int nch = Kd >> 5;

    {   // prologue
        float4 pa[4], pb[2];
        gemm_fetch(Afp, Bfp, bm, bn, kf4, 0, tid, pa, pb);
        gemm_store(smw, tid, pa, pb);
    }
    __syncthreads();

    for (int c = 0; c < nch; c++) {
        float4 pa[4], pb[2];
        if (c + 1 < nch) gemm_fetch(Afp, Bfp, bm, bn, kf4, c + 1, tid, pa, pb);
        gemm_compute(smw + (c & 1) * BUF_W, wrow, wcol, g, tig, acc);
        if (c + 1 < nch) {
            gemm_store(smw + ((c + 1) & 1) * BUF_W, tid, pa, pb);
            __syncthreads();
        }
    }

    // epilogue: c0,c1 -> (row, col..col+1); c2,c3 -> (row+8, col..col+1)
    #pragma unroll
    for (int mt = 0; mt < 2; mt++) {
        int row0 = bm + wrow + mt * 16 + g;
        #pragma unroll
        for (int nt = 0; nt < 4; nt++) {
            int col = bn + wcol + nt * 8 + 2 * tig;
            float* a4 = acc[mt][nt];
            float2 v0 = {a4[0] + bias[col], a4[1] + bias[col + 1]};
            float2 v1 = {a4[2] + bias[col], a4[3] + bias[col + 1]};
            if (MODE == 1) {
                float sc0 = scale[col], sc1 = scale[col + 1];
                float sh0 = shift[col], sh1 = shift[col + 1];
                float2 o0 = *(const float2*)(Oin + (size_t)row0 * ldc + col);
                float2 o1 = *(const float2*)(Oin + (size_t)(row0 + 8) * ldc + col);
                v0.x = fmaxf(v0.x, 0.f) * fmaxf(o0.x * sc0 + sh0, 0.f);
                v0.y = fmaxf(v0.y, 0.f) * fmaxf(o0.y * sc1 + sh1, 0.f);
                v1.x = fmaxf(v1.x, 0.f) * fmaxf(o1.x * sc0 + sh0, 0.f);
                v1.y = fmaxf(v1.y, 0.f) * fmaxf(o1.y * sc1 + sh1, 0.f);
            }
            *(float2*)(Cm + (size_t)row0 * ldc + coloff + col) = v0;
            *(float2*)(Cm + (size_t)(row0 + 8) * ldc + coloff + col) = v1;
        }
    }
}

// ---------------- small precompute kernels (fp32) ----------------
__global__ void precompute_vecs(const float* __restrict__ Wq, const float* __restrict__ bq,
                                const float* __restrict__ Wk, const float* __restrict__ bk,
                                const float* __restrict__ Wv, const float* __restrict__ bv,
                                const float* __restrict__ Wno, const float* __restrict__ bno) {
    int i = threadIdx.x;  // 256
    float a0 = 0.f, u = 0.f, b1 = 0.f;
    for (int o = 0; o < DOUT; o++) {
        a0 += Wk[o * DIN + i] * bq[o];
        u  += Wq[o * DIN + i] * bk[o];
        b1 += Wno[i * DOUT + o] * bv[o];
    }
    g_a0[i] = a0;
    g_u[i]  = u;
    g_b1[i] = b1 + bno[i];
    if (i == 0) {
        float c = 0.f;
        for (int o = 0; o < DOUT; o++) c += bk[o] * bq[o];
        g_c0[0] = c;
    }
}

__global__ void precompute_mats(const float* __restrict__ Wq, const float* __restrict__ Wk,
                                const float* __restrict__ Wv, const float* __restrict__ Wno) {
    __shared__ float colv[256];
    int r = blockIdx.x;
    int j = threadIdx.x;
    if (blockIdx.y == 0) {
        colv[j] = Wk[j * DIN + r];
        __syncthreads();
        float s = 0.f;
        #pragma unroll 8
        for (int o = 0; o < DOUT; o++) s += colv[o] * Wq[o * DIN + j];
        g_A[r * DIN + j] = s;
    } else {
        colv[j] = Wno[r * DOUT + j];
        __syncthreads();
        float s = 0.f;
        #pragma unroll 8
        for (int m = 0; m < DOUT; m++) s += colv[m] * Wv[m * DIN + j];
        g_B[r * DIN + j] = s;
    }
}

// C[n] = x_n . u + c0   (one warp per row)
__global__ void crow_kernel(const float* __restrict__ X) {
    int tid = threadIdx.x;
    int w = tid >> 5, lane = tid & 31;
    int row = blockIdx.x * 8 + w;
    const float* x = X + (size_t)row * DIN;
    float s = 0.f;
    #pragma unroll
    for (int j = 0; j < 8; j++) s += x[lane + 32 * j] * g_u[lane + 32 * j];
    #pragma unroll
    for (int off = 16; off; off >>= 1) s += __shfl_xor_sync(0xffffffffu, s, off);
    if (lane == 0) g_C[row] = s + g_c0[0];
}

// ---------------- attention: energies + softmax + weighted sum (one CTA/node) ----------------
#define XSTRIDE 264
__global__ void __launch_bounds__(256) attn_kernel(const float* __restrict__ nb) {
    __shared__ float xk[KN * XSTRIDE];
    __shared__ float qk[DIN];
    __shared__ float ek[KN];
    __shared__ float attw[KN];
    int n = blockIdx.x;
    int tid = threadIdx.x;

    const float4* src = (const float4*)(nb + (size_t)n * KN * DIN);
    #pragma unroll
    for (int j = 0; j < 8; j++) {
        int idx = tid + 256 * j;
        int k = idx >> 6;
        int m = idx & 63;
        float4 v = src[idx];
        *(float4*)(&xk[k * XSTRIDE + m * 4]) = v;
    }
    qk[tid] = g_QK[(size_t)n * DIN + tid];
    __syncthreads();

    int w = tid >> 5, lane = tid & 31;
    int k = (w << 2) + (lane >> 3);
    int cb = lane & 7;
    const float* row = &xk[k * XSTRIDE];
    float s = 0.f, rs = 0.f;
    #pragma unroll
    for (int j = 0; j < 32; j++) {
        float v = row[cb + 8 * j];
        s += v * qk[cb + 8 * j];
        rs += v;
    }
    s  += __shfl_down_sync(0xffffffffu, s, 4);
    rs += __shfl_down_sync(0xffffffffu, rs, 4);
    s  += __shfl_down_sync(0xffffffffu, s, 2);
    rs += __shfl_down_sync(0xffffffffu, rs, 2);
    s  += __shfl_down_sync(0xffffffffu, s, 1);
    rs += __shfl_down_sync(0xffffffffu, rs, 1);
    if ((lane & 7) == 0) {
        float e = s + g_C[n];
        ek[k] = (rs == 0.f) ? 1e-12f : e;
    }
    __syncthreads();

    if (w == 0) {
        float e = ek[lane];
        float m = e;
        #pragma unroll
        for (int off = 16; off; off >>= 1) m = fmaxf(m, __shfl_xor_sync(0xffffffffu, m, off));
        float ex = __expf(e - m);
        float sum = ex;
        #pragma unroll
        for (int off = 16; off; off >>= 1) sum += __shfl_xor_sync(0xffffffffu, sum, off);
        attw[lane] = ex / sum;
    }
    __syncthreads();

    float acc = 0.f;
    #pragma unroll
    for (int kk = 0; kk < KN; kk++) acc += attw[kk] * xk[kk * XSTRIDE + tid];
    g_S[(size_t)n * DIN + tid] = acc;
}

// ---------------- BatchNorm statistics (deterministic 2-stage) ----------------
__global__ void bn_stats() {
    int col = threadIdx.x;  // 512
    int blk = blockIdx.x;   // 128
    const float* p = g_O + (size_t)blk * 128 * DCAT + col;
    float s = 0.f, s2 = 0.f;
    #pragma unroll 4
    for (int r = 0; r < 128; r++) {
        float v = p[(size_t)r * DCAT];
        s += v; s2 += v * v;
    }
    g_psum[blk * DCAT + col] = s;
    g_psum2[blk * DCAT + col] = s2;
}

__global__ void bn_finalize(const float* __restrict__ gamma, const float* __restrict__ beta) {
    int col = threadIdx.x;  // 512
    float s = 0.f, s2 = 0.f;
    for (int b = 0; b < BN_BLOCKS; b++) {
        s += g_psum[b * DCAT + col];
        s2 += g_psum2[b * DCAT + col];
    }
    float mean = s * (1.f / NROWS);
    float var = s2 * (1.f / NROWS) - mean * mean;
    float sc = gamma[col] * rsqrtf(var + 1e-5f);
    g_scale[col] = sc;
    g_shift[col] = beta[col] - mean * sc;
}

// ---------------- launch ----------------
extern "C" void kernel_launch(void* const* d_in, const int* in_sizes, int n_in,
                              void* d_out, int out_size) {
    const float* X    = (const float*)d_in[0];
    const float* NB   = (const float*)d_in[1];
    const float* Wq   = (const float*)d_in[2];
    const float* bq   = (const float*)d_in[3];
    const float* Wk   = (const float*)d_in[4];
    const float* bk   = (const float*)d_in[5];
    const float* Wv   = (const float*)d_in[6];
    const float* bv   = (const float*)d_in[7];
    const float* Wno  = (const float*)d_in[8];
    const float* bno  = (const float*)d_in[9];
    const float* Wio  = (const float*)d_in[10];
    const float* bio  = (const float*)d_in[11];
    const float* Wg   = (const float*)d_in[12];
    const float* bg   = (const float*)d_in[13];
    const float* gam  = (const float*)d_in[14];
    const float* bet  = (const float*)d_in[15];
    float* out = (float*)d_out;

    float *pA, *pB, *pa0, *pb1, *pQK, *pS, *pO, *pscale, *pshift;
    cudaGetSymbolAddress((void**)&pA, g_A);
    cudaGetSymbolAddress((void**)&pB, g_B);
    cudaGetSymbolAddress((void**)&pa0, g_a0);
    cudaGetSymbolAddress((void**)&pb1, g_b1);
    cudaGetSymbolAddress((void**)&pQK, g_QK);
    cudaGetSymbolAddress((void**)&pS, g_S);
    cudaGetSymbolAddress((void**)&pO, g_O);
    cudaGetSymbolAddress((void**)&pscale, g_scale);
    cudaGetSymbolAddress((void**)&pshift, g_shift);

    const int smem_bytes = SMEM_WORDS * 4;  // 60KB -> 2 CTAs/SM
    cudaFuncSetAttribute(gemm_mma<0>, cudaFuncAttributeMaxDynamicSharedMemorySize, smem_bytes);
    cudaFuncSetAttribute(gemm_mma<1>, cudaFuncAttributeMaxDynamicSharedMemorySize, smem_bytes);

    // 1. tiny precomputes                                          (launch 1, 2)
    precompute_vecs<<<1, 256>>>(Wq, bq, Wk, bk, Wv, bv, Wno, bno);
    precompute_mats<<<dim3(256, 2), 256>>>(Wq, Wk, Wv, Wno);
    // 2. per-row energy constant                                   (launch 3)
    crow_kernel<<<NROWS / 8, 256>>>(X);
    // 3. QK = X A^T + a0                                           (launch 4)
    gemm_mma<0><<<dim3(4, 128), 256, smem_bytes>>>(X, pA, pa0, pQK, DIN, DIN, 0,
                                                   nullptr, nullptr, nullptr);
    // 4. O[:, :256] = X Wio^T + bio                                (launch 5)
    gemm_mma<0><<<dim3(4, 128), 256, smem_bytes>>>(X, Wio, bio, pO, DIN, DCAT, 0,
                                                   nullptr, nullptr, nullptr);
    // 5. attention  (position 6 -> captured by ncu -s 5 -c 1)      (launch 6)
    attn_kernel<<<NROWS, 256>>>(NB);
    // 6. O[:, 256:] = S B^T + b1                                   (launch 7)
    gemm_mma<0><<<dim3(4, 128), 256, smem_bytes>>>(pS, pB, pb1, pO, DIN, DCAT, DOUT,
                                                   nullptr, nullptr, nullptr);
    // 7. BN statistics                                             (launch 8, 9)
    bn_stats<<<BN_BLOCKS, DCAT>>>();
    bn_finalize<<<1, DCAT>>>(gam, bet);
    // 8. out = relu(O Wg^T + bg) * relu(BN(O))                     (launch 10)
    gemm_mma<1><<<dim3(8, 128), 256, smem_bytes>>>(pO, Wg, bg, out, DCAT, DCAT, 0,
                                                   pO, pscale, pshift);
}